// round 4
// baseline (speedup 1.0000x reference)
#include <cuda_runtime.h>
#include <cuda_bf16.h>
#include <float.h>

#define NPTS 8192
#define KNB  8      // k nearest neighbors
#define H0D  64
#define H1D  128
#define OUTC 256

// Scratch (static device globals; no allocation APIs)
__device__ int   g_idx[NPTS * KNB];
__device__ float g_a1[NPTS * H0D];
__device__ float g_c1[NPTS * H0D];
__device__ float g_x1[NPTS * H1D];
__device__ float g_a2[NPTS * H1D];
__device__ float g_c2[NPTS * H1D];

// ---------------------------------------------------------------------------
// KNN: brute force over all 8192 points (reference does joint KNN across batch)
// One thread per query point. Top-8 kept as sorted register list.
// grid 128 x block 64
// ---------------------------------------------------------------------------
__global__ void knn_kernel(const float* __restrict__ pts) {
    __shared__ float4 sP[512];
    const int tid = threadIdx.x;
    const int q = blockIdx.x * 64 + tid;

    const float qx = pts[q * 3 + 0];
    const float qy = pts[q * 3 + 1];
    const float qz = pts[q * 3 + 2];
    const float q2 = fmaf(qz, qz, fmaf(qy, qy, qx * qx));

    float kd[KNB];
    int   ki[KNB];
#pragma unroll
    for (int s = 0; s < KNB; ++s) { kd[s] = FLT_MAX; ki[s] = 0; }

    for (int t0 = 0; t0 < NPTS; t0 += 512) {
        __syncthreads();
        for (int j = tid; j < 512; j += 64) {
            float x = pts[(t0 + j) * 3 + 0];
            float y = pts[(t0 + j) * 3 + 1];
            float z = pts[(t0 + j) * 3 + 2];
            sP[j] = make_float4(x, y, z, fmaf(z, z, fmaf(y, y, x * x)));
        }
        __syncthreads();
#pragma unroll 4
        for (int j = 0; j < 512; ++j) {
            float4 p = sP[j];
            float dot = fmaf(qz, p.z, fmaf(qy, p.y, qx * p.x));
            float d = fmaf(-2.0f, dot, q2 + p.w);
            if (d < kd[KNB - 1]) {                 // strict: ties keep lower index
                kd[KNB - 1] = d; ki[KNB - 1] = t0 + j;
#pragma unroll
                for (int s = KNB - 1; s > 0; --s) {
                    if (kd[s] < kd[s - 1]) {
                        float td = kd[s]; kd[s] = kd[s - 1]; kd[s - 1] = td;
                        int   ti = ki[s]; ki[s] = ki[s - 1]; ki[s - 1] = ti;
                    } else break;
                }
            }
        }
    }
#pragma unroll
    for (int s = 0; s < KNB; ++s) g_idx[q * KNB + s] = ki[s];
}

// ---------------------------------------------------------------------------
// pre1: a1[i] = x_i @ (W1a - W1b) + b1 ; c1[j] = x_j @ W1b    (F=3 -> H0=64)
// one thread per (point, hidden unit). grid 2048 x block 256
// ---------------------------------------------------------------------------
__global__ void pre1_kernel(const float* __restrict__ pts,
                            const float* __restrict__ W1,
                            const float* __restrict__ b1) {
    int t = blockIdx.x * blockDim.x + threadIdx.x;
    int i = t >> 6;
    int h = t & 63;
    float x = pts[i * 3 + 0], y = pts[i * 3 + 1], z = pts[i * 3 + 2];
    float wa0 = W1[0 * 64 + h], wa1 = W1[1 * 64 + h], wa2 = W1[2 * 64 + h];
    float wb0 = W1[3 * 64 + h], wb1 = W1[4 * 64 + h], wb2 = W1[5 * 64 + h];
    float c = fmaf(z, wb2, fmaf(y, wb1, x * wb0));
    float a = fmaf(z, wa2 - wb2, fmaf(y, wa1 - wb1, x * (wa0 - wb0))) + b1[h];
    g_a1[t] = a;
    g_c1[t] = c;
}

// ---------------------------------------------------------------------------
// edge1: x1[i] = relu( max_k ( relu(a1[i] + c1[idx[i][k]]) @ W2 + b2 ) )
// GEMM: M=64 edges (8 points) x N=128 x K=64, fused relu-build + max epilogue.
// grid (1024) x block 256. 4x8 register tile per thread.
// ---------------------------------------------------------------------------
__global__ void edge1_kernel(const float* __restrict__ W2,
                             const float* __restrict__ b2) {
    __shared__ float As[32][64];
    __shared__ float Bs[32][128];
    __shared__ float sRed[16][128];
    __shared__ int   sIdx[64];

    const int tid = threadIdx.x;
    const int p0 = blockIdx.x * 8;

    if (tid < 64) sIdx[tid] = g_idx[p0 * KNB + tid];
    __syncthreads();

    const int tm = tid >> 4, tn = tid & 15;
    const int fm = tid & 63, fkq = tid >> 6;
    const float* __restrict__ arow = g_a1 + (p0 + (fm >> 3)) * H0D;
    const float* __restrict__ crow = g_c1 + sIdx[fm] * H0D;

    float acc[4][8];
#pragma unroll
    for (int m = 0; m < 4; ++m)
#pragma unroll
        for (int n = 0; n < 8; ++n) acc[m][n] = 0.f;

    for (int kb = 0; kb < 64; kb += 32) {
        float4 a0 = *(const float4*)(arow + kb + fkq * 8);
        float4 a1 = *(const float4*)(arow + kb + fkq * 8 + 4);
        float4 c0 = *(const float4*)(crow + kb + fkq * 8);
        float4 c1 = *(const float4*)(crow + kb + fkq * 8 + 4);
        As[fkq * 8 + 0][fm] = fmaxf(a0.x + c0.x, 0.f);
        As[fkq * 8 + 1][fm] = fmaxf(a0.y + c0.y, 0.f);
        As[fkq * 8 + 2][fm] = fmaxf(a0.z + c0.z, 0.f);
        As[fkq * 8 + 3][fm] = fmaxf(a0.w + c0.w, 0.f);
        As[fkq * 8 + 4][fm] = fmaxf(a1.x + c1.x, 0.f);
        As[fkq * 8 + 5][fm] = fmaxf(a1.y + c1.y, 0.f);
        As[fkq * 8 + 6][fm] = fmaxf(a1.z + c1.z, 0.f);
        As[fkq * 8 + 7][fm] = fmaxf(a1.w + c1.w, 0.f);
#pragma unroll
        for (int r = 0; r < 4; ++r) {
            int idx4 = tid + r * 256;
            int k = idx4 >> 5, c4 = idx4 & 31;
            *(float4*)&Bs[k][c4 * 4] = *(const float4*)(W2 + (kb + k) * 128 + c4 * 4);
        }
        __syncthreads();
#pragma unroll
        for (int k = 0; k < 32; ++k) {
            float4 av = *(const float4*)&As[k][tm * 4];
            float4 b0 = *(const float4*)&Bs[k][tn * 8];
            float4 b1 = *(const float4*)&Bs[k][tn * 8 + 4];
            float am[4] = {av.x, av.y, av.z, av.w};
            float bn[8] = {b0.x, b0.y, b0.z, b0.w, b1.x, b1.y, b1.z, b1.w};
#pragma unroll
            for (int m = 0; m < 4; ++m)
#pragma unroll
                for (int n = 0; n < 8; ++n) acc[m][n] = fmaf(am[m], bn[n], acc[m][n]);
        }
        __syncthreads();
    }

    // per-thread max over its 4 edges (all within one point), then pairwise merge
    float pm[8];
#pragma unroll
    for (int n = 0; n < 8; ++n)
        pm[n] = fmaxf(fmaxf(acc[0][n], acc[1][n]), fmaxf(acc[2][n], acc[3][n]));
#pragma unroll
    for (int n = 0; n < 8; ++n) sRed[tm][tn * 8 + n] = pm[n];
    __syncthreads();
    for (int r = tid; r < 8 * 128; r += 256) {
        int p = r >> 7, c = r & 127;
        float v = fmaxf(sRed[2 * p][c], sRed[2 * p + 1][c]) + b2[c];
        g_x1[(p0 + p) * H1D + c] = fmaxf(v, 0.f);
    }
}

// ---------------------------------------------------------------------------
// pre2: a2 = x1 @ (W3a - W3b) + b3 ; c2 = x1 @ W3b
// GEMM M=64 x N=128 x K=128; grid (128, 2) x block 256. y selects a2 vs c2.
// ---------------------------------------------------------------------------
__global__ void pre2_kernel(const float* __restrict__ W3,
                            const float* __restrict__ b3) {
    __shared__ float As[32][64];
    __shared__ float Bs[32][128];

    const int tid = threadIdx.x;
    const int r0 = blockIdx.x * 64;
    const int half = blockIdx.y;

    const int tm = tid >> 4, tn = tid & 15;
    const int fm = tid & 63, fkq = tid >> 6;
    const float* __restrict__ xrow = g_x1 + (r0 + fm) * H1D;

    float acc[4][8];
#pragma unroll
    for (int m = 0; m < 4; ++m)
#pragma unroll
        for (int n = 0; n < 8; ++n) acc[m][n] = 0.f;

    for (int kb = 0; kb < 128; kb += 32) {
        float4 a0 = *(const float4*)(xrow + kb + fkq * 8);
        float4 a1 = *(const float4*)(xrow + kb + fkq * 8 + 4);
        As[fkq * 8 + 0][fm] = a0.x;
        As[fkq * 8 + 1][fm] = a0.y;
        As[fkq * 8 + 2][fm] = a0.z;
        As[fkq * 8 + 3][fm] = a0.w;
        As[fkq * 8 + 4][fm] = a1.x;
        As[fkq * 8 + 5][fm] = a1.y;
        As[fkq * 8 + 6][fm] = a1.z;
        As[fkq * 8 + 7][fm] = a1.w;
#pragma unroll
        for (int r = 0; r < 4; ++r) {
            int idx4 = tid + r * 256;
            int k = idx4 >> 5, c4 = idx4 & 31;
            float4 vb = *(const float4*)(W3 + (128 + kb + k) * 128 + c4 * 4);
            if (half == 0) {
                float4 va = *(const float4*)(W3 + (kb + k) * 128 + c4 * 4);
                vb = make_float4(va.x - vb.x, va.y - vb.y, va.z - vb.z, va.w - vb.w);
            }
            *(float4*)&Bs[k][c4 * 4] = vb;
        }
        __syncthreads();
#pragma unroll
        for (int k = 0; k < 32; ++k) {
            float4 av = *(const float4*)&As[k][tm * 4];
            float4 b0 = *(const float4*)&Bs[k][tn * 8];
            float4 b1 = *(const float4*)&Bs[k][tn * 8 + 4];
            float am[4] = {av.x, av.y, av.z, av.w};
            float bn[8] = {b0.x, b0.y, b0.z, b0.w, b1.x, b1.y, b1.z, b1.w};
#pragma unroll
            for (int m = 0; m < 4; ++m)
#pragma unroll
                for (int n = 0; n < 8; ++n) acc[m][n] = fmaf(am[m], bn[n], acc[m][n]);
        }
        __syncthreads();
    }

    float* __restrict__ outp = half ? g_c2 : g_a2;
#pragma unroll
    for (int m = 0; m < 4; ++m) {
        int row = r0 + tm * 4 + m;
#pragma unroll
        for (int n = 0; n < 8; ++n) {
            int c = tn * 8 + n;
            float v = acc[m][n];
            if (half == 0) v += b3[c];
            outp[row * H1D + c] = v;
        }
    }
}

// ---------------------------------------------------------------------------
// edge2: out[i] = max_k ( relu(a2[i] + c2[idx[i][k]]) @ W4 ) + b4
// GEMM M=64 edges (8 points) x N=128 x K=128; grid (1024, 2) x block 256.
// ---------------------------------------------------------------------------
__global__ void edge2_kernel(const float* __restrict__ W4,
                             const float* __restrict__ b4,
                             float* __restrict__ out) {
    __shared__ float As[32][64];
    __shared__ float Bs[32][128];
    __shared__ float sRed[16][128];
    __shared__ int   sIdx[64];

    const int tid = threadIdx.x;
    const int p0 = blockIdx.x * 8;
    const int nb = blockIdx.y * 128;

    if (tid < 64) sIdx[tid] = g_idx[p0 * KNB + tid];
    __syncthreads();

    const int tm = tid >> 4, tn = tid & 15;
    const int fm = tid & 63, fkq = tid >> 6;
    const float* __restrict__ arow = g_a2 + (p0 + (fm >> 3)) * H1D;
    const float* __restrict__ crow = g_c2 + sIdx[fm] * H1D;

    float acc[4][8];
#pragma unroll
    for (int m = 0; m < 4; ++m)
#pragma unroll
        for (int n = 0; n < 8; ++n) acc[m][n] = 0.f;

    for (int kb = 0; kb < 128; kb += 32) {
        float4 a0 = *(const float4*)(arow + kb + fkq * 8);
        float4 a1 = *(const float4*)(arow + kb + fkq * 8 + 4);
        float4 c0 = *(const float4*)(crow + kb + fkq * 8);
        float4 c1 = *(const float4*)(crow + kb + fkq * 8 + 4);
        As[fkq * 8 + 0][fm] = fmaxf(a0.x + c0.x, 0.f);
        As[fkq * 8 + 1][fm] = fmaxf(a0.y + c0.y, 0.f);
        As[fkq * 8 + 2][fm] = fmaxf(a0.z + c0.z, 0.f);
        As[fkq * 8 + 3][fm] = fmaxf(a0.w + c0.w, 0.f);
        As[fkq * 8 + 4][fm] = fmaxf(a1.x + c1.x, 0.f);
        As[fkq * 8 + 5][fm] = fmaxf(a1.y + c1.y, 0.f);
        As[fkq * 8 + 6][fm] = fmaxf(a1.z + c1.z, 0.f);
        As[fkq * 8 + 7][fm] = fmaxf(a1.w + c1.w, 0.f);
#pragma unroll
        for (int r = 0; r < 4; ++r) {
            int idx4 = tid + r * 256;
            int k = idx4 >> 5, c4 = idx4 & 31;
            *(float4*)&Bs[k][c4 * 4] =
                *(const float4*)(W4 + (kb + k) * 256 + nb + c4 * 4);
        }
        __syncthreads();
#pragma unroll
        for (int k = 0; k < 32; ++k) {
            float4 av = *(const float4*)&As[k][tm * 4];
            float4 b0 = *(const float4*)&Bs[k][tn * 8];
            float4 b1 = *(const float4*)&Bs[k][tn * 8 + 4];
            float am[4] = {av.x, av.y, av.z, av.w};
            float bn[8] = {b0.x, b0.y, b0.z, b0.w, b1.x, b1.y, b1.z, b1.w};
#pragma unroll
            for (int m = 0; m < 4; ++m)
#pragma unroll
                for (int n = 0; n < 8; ++n) acc[m][n] = fmaf(am[m], bn[n], acc[m][n]);
        }
        __syncthreads();
    }

    float pm[8];
#pragma unroll
    for (int n = 0; n < 8; ++n)
        pm[n] = fmaxf(fmaxf(acc[0][n], acc[1][n]), fmaxf(acc[2][n], acc[3][n]));
#pragma unroll
    for (int n = 0; n < 8; ++n) sRed[tm][tn * 8 + n] = pm[n];
    __syncthreads();
    for (int r = tid; r < 8 * 128; r += 256) {
        int p = r >> 7, c = r & 127;
        float v = fmaxf(sRed[2 * p][c], sRed[2 * p + 1][c]) + b4[nb + c];
        out[(p0 + p) * OUTC + nb + c] = v;
    }
}

// ---------------------------------------------------------------------------
extern "C" void kernel_launch(void* const* d_in, const int* in_sizes, int n_in,
                              void* d_out, int out_size) {
    const float* pts = (const float*)d_in[0];
    const float* W1  = (const float*)d_in[1];
    const float* b1  = (const float*)d_in[2];
    const float* W2  = (const float*)d_in[3];
    const float* b2  = (const float*)d_in[4];
    const float* W3  = (const float*)d_in[5];
    const float* b3  = (const float*)d_in[6];
    const float* W4  = (const float*)d_in[7];
    const float* b4  = (const float*)d_in[8];
    float* out = (float*)d_out;

    knn_kernel<<<NPTS / 64, 64>>>(pts);
    pre1_kernel<<<NPTS * H0D / 256, 256>>>(pts, W1, b1);
    edge1_kernel<<<NPTS / 8, 256>>>(W2, b2);
    pre2_kernel<<<dim3(NPTS / 64, 2), 256>>>(W3, b3);
    edge2_kernel<<<dim3(NPTS / 8, 2), 256>>>(W4, b4, out);
}

// round 5
// speedup vs baseline: 1.9231x; 1.9231x over previous
#include <cuda_runtime.h>
#include <cuda_bf16.h>
#include <float.h>

#define NPTS 8192
#define KNB  8
#define H0D  64
#define H1D  128
#define OUTC 256

// Scratch (static device globals; no allocation APIs)
__device__ int   g_idx[NPTS * KNB];
__device__ float g_a1[NPTS * H0D];
__device__ float g_c1[NPTS * H0D];
__device__ float g_x1[NPTS * H1D];
__device__ float g_a2[NPTS * H1D];
__device__ float g_c2[NPTS * H1D];

// ---------------------------------------------------------------------------
// KNN v2: 32 queries per block, 8 threads per query. Each thread scans an
// interleaved 1/8 shard of all 8192 candidates keeping a lex-sorted top-8;
// one thread per query merges the 64 partials with (d, idx) lexicographic
// ordering (matches jax top_k stable tie-break). grid 256 x block 256.
// ---------------------------------------------------------------------------
__global__ void knn_kernel(const float* __restrict__ pts) {
    __shared__ float4 sP[512];
    __shared__ float  sD[32][65];
    __shared__ int    sI[32][65];

    const int tid = threadIdx.x;
    const int ql = tid >> 3;        // query lane 0..31
    const int sh = tid & 7;         // shard 0..7
    const int q = blockIdx.x * 32 + ql;

    const float qx = pts[q * 3 + 0];
    const float qy = pts[q * 3 + 1];
    const float qz = pts[q * 3 + 2];
    const float q2 = fmaf(qz, qz, fmaf(qy, qy, qx * qx));

    float kd[KNB];
    int   ki[KNB];
#pragma unroll
    for (int s = 0; s < KNB; ++s) { kd[s] = FLT_MAX; ki[s] = 0x7fffffff; }

    for (int t0 = 0; t0 < NPTS; t0 += 512) {
        __syncthreads();
        for (int j = tid; j < 512; j += 256) {
            float x = pts[(t0 + j) * 3 + 0];
            float y = pts[(t0 + j) * 3 + 1];
            float z = pts[(t0 + j) * 3 + 2];
            sP[j] = make_float4(x, y, z, fmaf(z, z, fmaf(y, y, x * x)));
        }
        __syncthreads();
#pragma unroll 4
        for (int jj = sh; jj < 512; jj += 8) {
            float4 p = sP[jj];
            float dot = fmaf(qz, p.z, fmaf(qy, p.y, qx * p.x));
            float d = fmaf(-2.0f, dot, q2 + p.w);
            if (d < kd[KNB - 1]) {          // strict: equal-d keeps earlier index
                kd[KNB - 1] = d; ki[KNB - 1] = t0 + jj;
#pragma unroll
                for (int s = KNB - 1; s > 0; --s) {
                    if (kd[s] < kd[s - 1]) {
                        float td = kd[s]; kd[s] = kd[s - 1]; kd[s - 1] = td;
                        int   ti = ki[s]; ki[s] = ki[s - 1]; ki[s - 1] = ti;
                    } else break;
                }
            }
        }
    }
#pragma unroll
    for (int s = 0; s < KNB; ++s) {
        sD[ql][sh * 8 + s] = kd[s];
        sI[ql][sh * 8 + s] = ki[s];
    }
    __syncthreads();

    if (tid < 32) {
        float md[KNB];
        int   mi[KNB];
#pragma unroll
        for (int s = 0; s < KNB; ++s) { md[s] = FLT_MAX; mi[s] = 0x7fffffff; }
        for (int e = 0; e < 64; ++e) {
            float d = sD[tid][e];
            int   i = sI[tid][e];
            if (d < md[KNB - 1] || (d == md[KNB - 1] && i < mi[KNB - 1])) {
                md[KNB - 1] = d; mi[KNB - 1] = i;
#pragma unroll
                for (int s = KNB - 1; s > 0; --s) {
                    if (md[s] < md[s - 1] ||
                        (md[s] == md[s - 1] && mi[s] < mi[s - 1])) {
                        float td = md[s]; md[s] = md[s - 1]; md[s - 1] = td;
                        int   ti = mi[s]; mi[s] = mi[s - 1]; mi[s - 1] = ti;
                    } else break;
                }
            }
        }
        int qq = blockIdx.x * 32 + tid;
#pragma unroll
        for (int s = 0; s < KNB; ++s) g_idx[qq * KNB + s] = mi[s];
    }
}

// ---------------------------------------------------------------------------
// pre1: a1[i] = x_i @ (W1a - W1b) + b1 ; c1[j] = x_j @ W1b    (F=3 -> 64)
// ---------------------------------------------------------------------------
__global__ void pre1_kernel(const float* __restrict__ pts,
                            const float* __restrict__ W1,
                            const float* __restrict__ b1) {
    int t = blockIdx.x * blockDim.x + threadIdx.x;
    int i = t >> 6;
    int h = t & 63;
    float x = pts[i * 3 + 0], y = pts[i * 3 + 1], z = pts[i * 3 + 2];
    float wa0 = W1[0 * 64 + h], wa1 = W1[1 * 64 + h], wa2 = W1[2 * 64 + h];
    float wb0 = W1[3 * 64 + h], wb1 = W1[4 * 64 + h], wb2 = W1[5 * 64 + h];
    float c = fmaf(z, wb2, fmaf(y, wb1, x * wb0));
    float a = fmaf(z, wa2 - wb2, fmaf(y, wa1 - wb1, x * (wa0 - wb0))) + b1[h];
    g_a1[t] = a;
    g_c1[t] = c;
}

// ---------------------------------------------------------------------------
// edge1: x1[i] = relu( max_k( relu(a1[i]+c1[idx[i][k]]) @ W2 + b2 ) )
// M=128 edges (16 points), N=128, K=64. 8x8 register tile, conflict-free
// split fragments. grid 512 x block 256.
// ---------------------------------------------------------------------------
__global__ void __launch_bounds__(256, 2)
edge1_kernel(const float* __restrict__ W2, const float* __restrict__ b2) {
    __shared__ float sm[8192];          // As = sm[0..4095], Bs = sm[4096..]
    __shared__ int   sIdx[128];
    float* As = sm;
    float* Bs = sm + 4096;

    const int tid = threadIdx.x;
    const int p0 = blockIdx.x * 16;

    if (tid < 128) sIdx[tid] = g_idx[p0 * KNB + tid];
    __syncthreads();

    const int tm = tid >> 4, tn = tid & 15;
    const int fm = tid & 127, fq = tid >> 7;
    const float* __restrict__ arow = g_a1 + (p0 + (fm >> 3)) * H0D;
    const float* __restrict__ crow = g_c1 + sIdx[fm] * H0D;

    float acc[8][8];
#pragma unroll
    for (int m = 0; m < 8; ++m)
#pragma unroll
        for (int n = 0; n < 8; ++n) acc[m][n] = 0.f;

#pragma unroll
    for (int kb = 0; kb < 64; kb += 32) {
        int base = kb + fq * 16;
#pragma unroll
        for (int u = 0; u < 4; ++u) {
            float4 a = *(const float4*)(arow + base + u * 4);
            float4 c = *(const float4*)(crow + base + u * 4);
            int k0 = fq * 16 + u * 4;
            As[(k0 + 0) * 128 + fm] = fmaxf(a.x + c.x, 0.f);
            As[(k0 + 1) * 128 + fm] = fmaxf(a.y + c.y, 0.f);
            As[(k0 + 2) * 128 + fm] = fmaxf(a.z + c.z, 0.f);
            As[(k0 + 3) * 128 + fm] = fmaxf(a.w + c.w, 0.f);
        }
#pragma unroll
        for (int r = 0; r < 4; ++r) {
            int f = tid + r * 256;
            int k = f >> 5, c4 = f & 31;
            *(float4*)&Bs[k * 128 + c4 * 4] =
                *(const float4*)(W2 + (kb + k) * 128 + c4 * 4);
        }
        __syncthreads();
#pragma unroll
        for (int k = 0; k < 32; ++k) {
            float4 aLo = *(const float4*)&As[k * 128 + tm * 4];
            float4 aHi = *(const float4*)&As[k * 128 + 64 + tm * 4];
            float4 bLo = *(const float4*)&Bs[k * 128 + tn * 4];
            float4 bHi = *(const float4*)&Bs[k * 128 + 64 + tn * 4];
            float a[8] = {aLo.x, aLo.y, aLo.z, aLo.w, aHi.x, aHi.y, aHi.z, aHi.w};
            float b[8] = {bLo.x, bLo.y, bLo.z, bLo.w, bHi.x, bHi.y, bHi.z, bHi.w};
#pragma unroll
            for (int m = 0; m < 8; ++m)
#pragma unroll
                for (int n = 0; n < 8; ++n) acc[m][n] = fmaf(a[m], b[n], acc[m][n]);
        }
        __syncthreads();
    }

    // epilogue: max over 4 edges per half, stash in sRed (aliased over sm)
    float pmLo[8], pmHi[8];
#pragma unroll
    for (int n = 0; n < 8; ++n) {
        pmLo[n] = fmaxf(fmaxf(acc[0][n], acc[1][n]), fmaxf(acc[2][n], acc[3][n]));
        pmHi[n] = fmaxf(fmaxf(acc[4][n], acc[5][n]), fmaxf(acc[6][n], acc[7][n]));
    }
    // sRed rows 0..15: point tm>>1 (lo), rows 16..31: point 8+(tm>>1) (hi); stride 132
    *(float4*)&sm[tm * 132 + tn * 4]            = make_float4(pmLo[0], pmLo[1], pmLo[2], pmLo[3]);
    *(float4*)&sm[tm * 132 + 64 + tn * 4]       = make_float4(pmLo[4], pmLo[5], pmLo[6], pmLo[7]);
    *(float4*)&sm[(16 + tm) * 132 + tn * 4]     = make_float4(pmHi[0], pmHi[1], pmHi[2], pmHi[3]);
    *(float4*)&sm[(16 + tm) * 132 + 64 + tn * 4] = make_float4(pmHi[4], pmHi[5], pmHi[6], pmHi[7]);
    __syncthreads();
    for (int r = tid; r < 2048; r += 256) {
        int p = r >> 7, c = r & 127;
        int rr = (p < 8) ? (2 * p) : (16 + 2 * (p - 8));
        float v = fmaxf(sm[rr * 132 + c], sm[(rr + 1) * 132 + c]) + b2[c];
        g_x1[(p0 + p) * H1D + c] = fmaxf(v, 0.f);
    }
}

// ---------------------------------------------------------------------------
// pre2: a2 = x1 @ (W3a - W3b) + b3 ; c2 = x1 @ W3b
// M=128, N=128, K=128. grid (64, 2) x block 256.
// ---------------------------------------------------------------------------
__global__ void __launch_bounds__(256, 2)
pre2_kernel(const float* __restrict__ W3, const float* __restrict__ b3) {
    __shared__ float sm[8192];
    float* As = sm;
    float* Bs = sm + 4096;

    const int tid = threadIdx.x;
    const int r0 = blockIdx.x * 128;
    const int half = blockIdx.y;

    const int tm = tid >> 4, tn = tid & 15;
    const int fm = tid & 127, fq = tid >> 7;
    const float* __restrict__ xrow = g_x1 + (r0 + fm) * H1D;

    float acc[8][8];
#pragma unroll
    for (int m = 0; m < 8; ++m)
#pragma unroll
        for (int n = 0; n < 8; ++n) acc[m][n] = 0.f;

#pragma unroll
    for (int kb = 0; kb < 128; kb += 32) {
        int base = kb + fq * 16;
#pragma unroll
        for (int u = 0; u < 4; ++u) {
            float4 a = *(const float4*)(xrow + base + u * 4);
            int k0 = fq * 16 + u * 4;
            As[(k0 + 0) * 128 + fm] = a.x;
            As[(k0 + 1) * 128 + fm] = a.y;
            As[(k0 + 2) * 128 + fm] = a.z;
            As[(k0 + 3) * 128 + fm] = a.w;
        }
#pragma unroll
        for (int r = 0; r < 4; ++r) {
            int f = tid + r * 256;
            int k = f >> 5, c4 = f & 31;
            float4 vb = *(const float4*)(W3 + (128 + kb + k) * 128 + c4 * 4);
            if (half == 0) {
                float4 va = *(const float4*)(W3 + (kb + k) * 128 + c4 * 4);
                vb = make_float4(va.x - vb.x, va.y - vb.y, va.z - vb.z, va.w - vb.w);
            }
            *(float4*)&Bs[k * 128 + c4 * 4] = vb;
        }
        __syncthreads();
#pragma unroll
        for (int k = 0; k < 32; ++k) {
            float4 aLo = *(const float4*)&As[k * 128 + tm * 4];
            float4 aHi = *(const float4*)&As[k * 128 + 64 + tm * 4];
            float4 bLo = *(const float4*)&Bs[k * 128 + tn * 4];
            float4 bHi = *(const float4*)&Bs[k * 128 + 64 + tn * 4];
            float a[8] = {aLo.x, aLo.y, aLo.z, aLo.w, aHi.x, aHi.y, aHi.z, aHi.w};
            float b[8] = {bLo.x, bLo.y, bLo.z, bLo.w, bHi.x, bHi.y, bHi.z, bHi.w};
#pragma unroll
            for (int m = 0; m < 8; ++m)
#pragma unroll
                for (int n = 0; n < 8; ++n) acc[m][n] = fmaf(a[m], b[n], acc[m][n]);
        }
        __syncthreads();
    }

    float* __restrict__ outp = half ? g_c2 : g_a2;
#pragma unroll
    for (int m = 0; m < 8; ++m) {
        int row = r0 + ((m < 4) ? (tm * 4 + m) : (64 + tm * 4 + m - 4));
#pragma unroll
        for (int half_n = 0; half_n < 2; ++half_n) {
            int c0 = half_n * 64 + tn * 4;
            float4 v;
            v.x = acc[m][half_n * 4 + 0];
            v.y = acc[m][half_n * 4 + 1];
            v.z = acc[m][half_n * 4 + 2];
            v.w = acc[m][half_n * 4 + 3];
            if (half == 0) {
                v.x += b3[c0 + 0]; v.y += b3[c0 + 1];
                v.z += b3[c0 + 2]; v.w += b3[c0 + 3];
            }
            *(float4*)&outp[row * H1D + c0] = v;
        }
    }
}

// ---------------------------------------------------------------------------
// edge2: out[i] = max_k( relu(a2[i]+c2[idx[i][k]]) @ W4 ) + b4
// M=128 edges (16 points), N=128 (half of 256), K=128. grid (512, 2) x 256.
// ---------------------------------------------------------------------------
__global__ void __launch_bounds__(256, 2)
edge2_kernel(const float* __restrict__ W4, const float* __restrict__ b4,
             float* __restrict__ out) {
    __shared__ float sm[8192];
    __shared__ int   sIdx[128];
    float* As = sm;
    float* Bs = sm + 4096;

    const int tid = threadIdx.x;
    const int p0 = blockIdx.x * 16;
    const int nb = blockIdx.y * 128;

    if (tid < 128) sIdx[tid] = g_idx[p0 * KNB + tid];
    __syncthreads();

    const int tm = tid >> 4, tn = tid & 15;
    const int fm = tid & 127, fq = tid >> 7;
    const float* __restrict__ arow = g_a2 + (p0 + (fm >> 3)) * H1D;
    const float* __restrict__ crow = g_c2 + sIdx[fm] * H1D;

    float acc[8][8];
#pragma unroll
    for (int m = 0; m < 8; ++m)
#pragma unroll
        for (int n = 0; n < 8; ++n) acc[m][n] = 0.f;

#pragma unroll
    for (int kb = 0; kb < 128; kb += 32) {
        int base = kb + fq * 16;
#pragma unroll
        for (int u = 0; u < 4; ++u) {
            float4 a = *(const float4*)(arow + base + u * 4);
            float4 c = *(const float4*)(crow + base + u * 4);
            int k0 = fq * 16 + u * 4;
            As[(k0 + 0) * 128 + fm] = fmaxf(a.x + c.x, 0.f);
            As[(k0 + 1) * 128 + fm] = fmaxf(a.y + c.y, 0.f);
            As[(k0 + 2) * 128 + fm] = fmaxf(a.z + c.z, 0.f);
            As[(k0 + 3) * 128 + fm] = fmaxf(a.w + c.w, 0.f);
        }
#pragma unroll
        for (int r = 0; r < 4; ++r) {
            int f = tid + r * 256;
            int k = f >> 5, c4 = f & 31;
            *(float4*)&Bs[k * 128 + c4 * 4] =
                *(const float4*)(W4 + (kb + k) * 256 + nb + c4 * 4);
        }
        __syncthreads();
#pragma unroll
        for (int k = 0; k < 32; ++k) {
            float4 aLo = *(const float4*)&As[k * 128 + tm * 4];
            float4 aHi = *(const float4*)&As[k * 128 + 64 + tm * 4];
            float4 bLo = *(const float4*)&Bs[k * 128 + tn * 4];
            float4 bHi = *(const float4*)&Bs[k * 128 + 64 + tn * 4];
            float a[8] = {aLo.x, aLo.y, aLo.z, aLo.w, aHi.x, aHi.y, aHi.z, aHi.w};
            float b[8] = {bLo.x, bLo.y, bLo.z, bLo.w, bHi.x, bHi.y, bHi.z, bHi.w};
#pragma unroll
            for (int m = 0; m < 8; ++m)
#pragma unroll
                for (int n = 0; n < 8; ++n) acc[m][n] = fmaf(a[m], b[n], acc[m][n]);
        }
        __syncthreads();
    }

    float pmLo[8], pmHi[8];
#pragma unroll
    for (int n = 0; n < 8; ++n) {
        pmLo[n] = fmaxf(fmaxf(acc[0][n], acc[1][n]), fmaxf(acc[2][n], acc[3][n]));
        pmHi[n] = fmaxf(fmaxf(acc[4][n], acc[5][n]), fmaxf(acc[6][n], acc[7][n]));
    }
    *(float4*)&sm[tm * 132 + tn * 4]             = make_float4(pmLo[0], pmLo[1], pmLo[2], pmLo[3]);
    *(float4*)&sm[tm * 132 + 64 + tn * 4]        = make_float4(pmLo[4], pmLo[5], pmLo[6], pmLo[7]);
    *(float4*)&sm[(16 + tm) * 132 + tn * 4]      = make_float4(pmHi[0], pmHi[1], pmHi[2], pmHi[3]);
    *(float4*)&sm[(16 + tm) * 132 + 64 + tn * 4] = make_float4(pmHi[4], pmHi[5], pmHi[6], pmHi[7]);
    __syncthreads();
    for (int r = tid; r < 2048; r += 256) {
        int p = r >> 7, c = r & 127;
        int rr = (p < 8) ? (2 * p) : (16 + 2 * (p - 8));
        float v = fmaxf(sm[rr * 132 + c], sm[(rr + 1) * 132 + c]) + b4[nb + c];
        out[(p0 + p) * OUTC + nb + c] = v;
    }
}

// ---------------------------------------------------------------------------
extern "C" void kernel_launch(void* const* d_in, const int* in_sizes, int n_in,
                              void* d_out, int out_size) {
    const float* pts = (const float*)d_in[0];
    const float* W1  = (const float*)d_in[1];
    const float* b1  = (const float*)d_in[2];
    const float* W2  = (const float*)d_in[3];
    const float* b2  = (const float*)d_in[4];
    const float* W3  = (const float*)d_in[5];
    const float* b3  = (const float*)d_in[6];
    const float* W4  = (const float*)d_in[7];
    const float* b4  = (const float*)d_in[8];
    float* out = (float*)d_out;

    knn_kernel<<<NPTS / 32, 256>>>(pts);
    pre1_kernel<<<NPTS * H0D / 256, 256>>>(pts, W1, b1);
    edge1_kernel<<<NPTS / 16, 256>>>(W2, b2);
    pre2_kernel<<<dim3(NPTS / 128, 2), 256>>>(W3, b3);
    edge2_kernel<<<dim3(NPTS / 16, 2), 256>>>(W4, b4, out);
}

// round 6
// speedup vs baseline: 2.3231x; 1.2080x over previous
#include <cuda_runtime.h>
#include <cuda_bf16.h>
#include <float.h>
#include <stdint.h>

#define NPTS 8192
#define KNB  8
#define H0D  64
#define H1D  128
#define OUTC 256
#define SA   40          // smem row stride (bf16) -> conflict-free fragment LDS

// ---------------- scratch (static device globals) ----------------
__device__ int   g_idx[NPTS * KNB];
__device__ float g_a1[NPTS * H0D];
__device__ float g_c1[NPTS * H0D];
__device__ float g_x1[NPTS * H1D];
__device__ float g_a2[NPTS * H1D];
__device__ float g_c2[NPTS * H1D];

// weights: bf16 hi/lo split, transposed to [N][K]
__device__ __nv_bfloat16 g_w2t_hi[H1D * H0D],     g_w2t_lo[H1D * H0D];      // [128][64]
__device__ __nv_bfloat16 g_w3t_hi[2 * H1D * H1D], g_w3t_lo[2 * H1D * H1D];  // [2][128][128]
__device__ __nv_bfloat16 g_w4t_hi[OUTC * H1D],    g_w4t_lo[OUTC * H1D];     // [256][128]

// ---------------- helpers ----------------
__device__ __forceinline__ void bsplit(float v, __nv_bfloat16& h, __nv_bfloat16& l) {
    h = __float2bfloat16_rn(v);
    l = __float2bfloat16_rn(v - __bfloat162float(h));
}

__device__ __forceinline__ void mma16816(float* c, const uint32_t* a, const uint32_t* b) {
    asm volatile(
        "mma.sync.aligned.m16n8k16.row.col.f32.bf16.bf16.f32 "
        "{%0,%1,%2,%3}, {%4,%5,%6,%7}, {%8,%9}, {%0,%1,%2,%3};\n"
        : "+f"(c[0]), "+f"(c[1]), "+f"(c[2]), "+f"(c[3])
        : "r"(a[0]), "r"(a[1]), "r"(a[2]), "r"(a[3]), "r"(b[0]), "r"(b[1]));
}

// ---------------------------------------------------------------------------
// weight prep: split fp32 weights to bf16 hi/lo, transpose to [N][K]
// ---------------------------------------------------------------------------
__global__ void prep_w2(const float* __restrict__ W2) {
    int t = blockIdx.x * 256 + threadIdx.x;      // 8192 = 128n * 64k
    int n = t >> 6, k = t & 63;
    bsplit(W2[k * H1D + n], g_w2t_hi[t], g_w2t_lo[t]);
}
__global__ void prep_w3(const float* __restrict__ W3) {
    int t = blockIdx.x * 256 + threadIdx.x;      // 32768 = 2 * 128n * 128k
    int half = t >> 14; int r = t & 16383; int n = r >> 7; int k = r & 127;
    float v = W3[(H1D + k) * H1D + n];
    if (half == 0) v = W3[k * H1D + n] - v;
    bsplit(v, g_w3t_hi[t], g_w3t_lo[t]);
}
__global__ void prep_w4(const float* __restrict__ W4) {
    int t = blockIdx.x * 256 + threadIdx.x;      // 32768 = 256n * 128k
    int n = t >> 7, k = t & 127;
    bsplit(W4[k * OUTC + n], g_w4t_hi[t], g_w4t_lo[t]);
}

// ---------------------------------------------------------------------------
// KNN (unchanged from r4): 32 queries/block, 8 threads/query.
// ---------------------------------------------------------------------------
__global__ void knn_kernel(const float* __restrict__ pts) {
    __shared__ float4 sP[512];
    __shared__ float  sD[32][65];
    __shared__ int    sI[32][65];

    const int tid = threadIdx.x;
    const int ql = tid >> 3, sh = tid & 7;
    const int q = blockIdx.x * 32 + ql;

    const float qx = pts[q * 3 + 0], qy = pts[q * 3 + 1], qz = pts[q * 3 + 2];
    const float q2 = fmaf(qz, qz, fmaf(qy, qy, qx * qx));

    float kd[KNB]; int ki[KNB];
#pragma unroll
    for (int s = 0; s < KNB; ++s) { kd[s] = FLT_MAX; ki[s] = 0x7fffffff; }

    for (int t0 = 0; t0 < NPTS; t0 += 512) {
        __syncthreads();
        for (int j = tid; j < 512; j += 256) {
            float x = pts[(t0 + j) * 3 + 0];
            float y = pts[(t0 + j) * 3 + 1];
            float z = pts[(t0 + j) * 3 + 2];
            sP[j] = make_float4(x, y, z, fmaf(z, z, fmaf(y, y, x * x)));
        }
        __syncthreads();
#pragma unroll 4
        for (int jj = sh; jj < 512; jj += 8) {
            float4 p = sP[jj];
            float dot = fmaf(qz, p.z, fmaf(qy, p.y, qx * p.x));
            float d = fmaf(-2.0f, dot, q2 + p.w);
            if (d < kd[KNB - 1]) {
                kd[KNB - 1] = d; ki[KNB - 1] = t0 + jj;
#pragma unroll
                for (int s = KNB - 1; s > 0; --s) {
                    if (kd[s] < kd[s - 1]) {
                        float td = kd[s]; kd[s] = kd[s - 1]; kd[s - 1] = td;
                        int   ti = ki[s]; ki[s] = ki[s - 1]; ki[s - 1] = ti;
                    } else break;
                }
            }
        }
    }
#pragma unroll
    for (int s = 0; s < KNB; ++s) { sD[ql][sh * 8 + s] = kd[s]; sI[ql][sh * 8 + s] = ki[s]; }
    __syncthreads();

    if (tid < 32) {
        float md[KNB]; int mi[KNB];
#pragma unroll
        for (int s = 0; s < KNB; ++s) { md[s] = FLT_MAX; mi[s] = 0x7fffffff; }
        for (int e = 0; e < 64; ++e) {
            float d = sD[tid][e]; int i = sI[tid][e];
            if (d < md[KNB - 1] || (d == md[KNB - 1] && i < mi[KNB - 1])) {
                md[KNB - 1] = d; mi[KNB - 1] = i;
#pragma unroll
                for (int s = KNB - 1; s > 0; --s) {
                    if (md[s] < md[s - 1] || (md[s] == md[s - 1] && mi[s] < mi[s - 1])) {
                        float td = md[s]; md[s] = md[s - 1]; md[s - 1] = td;
                        int   ti = mi[s]; mi[s] = mi[s - 1]; mi[s - 1] = ti;
                    } else break;
                }
            }
        }
        int qq = blockIdx.x * 32 + tid;
#pragma unroll
        for (int s = 0; s < KNB; ++s) g_idx[qq * KNB + s] = mi[s];
    }
}

// ---------------------------------------------------------------------------
// pre1 (unchanged)
// ---------------------------------------------------------------------------
__global__ void pre1_kernel(const float* __restrict__ pts,
                            const float* __restrict__ W1,
                            const float* __restrict__ b1) {
    int t = blockIdx.x * blockDim.x + threadIdx.x;
    int i = t >> 6, h = t & 63;
    float x = pts[i * 3 + 0], y = pts[i * 3 + 1], z = pts[i * 3 + 2];
    float wa0 = W1[0 * 64 + h], wa1 = W1[1 * 64 + h], wa2 = W1[2 * 64 + h];
    float wb0 = W1[3 * 64 + h], wb1 = W1[4 * 64 + h], wb2 = W1[5 * 64 + h];
    float c = fmaf(z, wb2, fmaf(y, wb1, x * wb0));
    float a = fmaf(z, wa2 - wb2, fmaf(y, wa1 - wb1, x * (wa0 - wb0))) + b1[h];
    g_a1[t] = a;
    g_c1[t] = c;
}

// ===========================================================================
// Tensor-core edge GEMM (shared by edge1/edge2 via macro-ish duplication).
// Block: M=128 edges (16 pts) x N=128, K staged in 32-chunks.
// 8 warps: wm=wid&3 (32-row tiles), wn=wid>>2 (64-col tiles).
// 3-term bf16 split: Ahi*Bhi + Ahi*Blo + Alo*Bhi.
// ===========================================================================

#define GEMM_CORE(KDIM, A_BUILD)                                                   \
    const int tid = threadIdx.x;                                                   \
    const int lane = tid & 31, wid = tid >> 5;                                     \
    const int g = lane >> 2, tig = lane & 3;                                       \
    const int wm = wid & 3, wn = wid >> 2;                                         \
    const int fm = tid & 127, fq = tid >> 7;                                       \
    float acc[2][8][4];                                                            \
    _Pragma("unroll") for (int mb = 0; mb < 2; ++mb)                               \
    _Pragma("unroll") for (int nt = 0; nt < 8; ++nt)                               \
    _Pragma("unroll") for (int e = 0; e < 4; ++e) acc[mb][nt][e] = 0.f;            \
    for (int kb = 0; kb < (KDIM); kb += 32) {                                      \
        { A_BUILD }                                                                \
        {   /* stage B: [n][k] rows, 16 bf16 per thread per buffer */              \
            const __nv_bfloat16* bh = Bhi_g + fm * (KDIM) + kb + fq * 16;          \
            const __nv_bfloat16* bl = Blo_g + fm * (KDIM) + kb + fq * 16;          \
            int o = fm * SA + fq * 16;                                             \
            *(uint4*)&sBhi[o]     = *(const uint4*)(bh);                           \
            *(uint4*)&sBhi[o + 8] = *(const uint4*)(bh + 8);                       \
            *(uint4*)&sBlo[o]     = *(const uint4*)(bl);                           \
            *(uint4*)&sBlo[o + 8] = *(const uint4*)(bl + 8);                       \
        }                                                                          \
        __syncthreads();                                                           \
        _Pragma("unroll")                                                          \
        for (int ks = 0; ks < 2; ++ks) {                                           \
            const int kc = ks * 16;                                                \
            _Pragma("unroll")                                                      \
            for (int t = 0; t < 3; ++t) {                                          \
                const __nv_bfloat16* Ap = (t == 2) ? sAlo : sAhi;                  \
                const __nv_bfloat16* Bp = (t == 1) ? sBlo : sBhi;                  \
                uint32_t af[2][4];                                                 \
                _Pragma("unroll")                                                  \
                for (int mb = 0; mb < 2; ++mb) {                                   \
                    int r = (wm * 32 + mb * 16 + g) * SA + kc + tig * 2;           \
                    af[mb][0] = *(const uint32_t*)(Ap + r);                        \
                    af[mb][1] = *(const uint32_t*)(Ap + r + 8 * SA);               \
                    af[mb][2] = *(const uint32_t*)(Ap + r + 8);                    \
                    af[mb][3] = *(const uint32_t*)(Ap + r + 8 * SA + 8);           \
                }                                                                  \
                uint32_t bf[8][2];                                                 \
                _Pragma("unroll")                                                  \
                for (int nt = 0; nt < 8; ++nt) {                                   \
                    int rB = (wn * 64 + nt * 8 + g) * SA + kc + tig * 2;           \
                    bf[nt][0] = *(const uint32_t*)(Bp + rB);                       \
                    bf[nt][1] = *(const uint32_t*)(Bp + rB + 8);                   \
                }                                                                  \
                _Pragma("unroll")                                                  \
                for (int mb = 0; mb < 2; ++mb)                                     \
                _Pragma("unroll")                                                  \
                for (int nt = 0; nt < 8; ++nt)                                     \
                    mma16816(acc[mb][nt], af[mb], bf[nt]);                         \
            }                                                                      \
        }                                                                          \
        __syncthreads();                                                           \
    }

#define EDGE_A_BUILD(KDIM, ASRC, CSRC)                                             \
    const float* __restrict__ arow = (ASRC) + (p0 + (fm >> 3)) * (KDIM);           \
    const float* __restrict__ crow = (CSRC) + sIdx[fm] * (KDIM);                   \
    _Pragma("unroll")                                                              \
    for (int u = 0; u < 4; ++u) {                                                  \
        float4 a = *(const float4*)(arow + kb + fq * 16 + u * 4);                  \
        float4 c = *(const float4*)(crow + kb + fq * 16 + u * 4);                  \
        float v0 = fmaxf(a.x + c.x, 0.f), v1 = fmaxf(a.y + c.y, 0.f);              \
        float v2 = fmaxf(a.z + c.z, 0.f), v3 = fmaxf(a.w + c.w, 0.f);              \
        __nv_bfloat16 h0, l0, h1, l1, h2, l2, h3, l3;                              \
        bsplit(v0, h0, l0); bsplit(v1, h1, l1);                                    \
        bsplit(v2, h2, l2); bsplit(v3, h3, l3);                                    \
        int o = fm * SA + fq * 16 + u * 4;                                         \
        __nv_bfloat162 p01; p01.x = h0; p01.y = h1;                                \
        __nv_bfloat162 p23; p23.x = h2; p23.y = h3;                                \
        *(__nv_bfloat162*)&sAhi[o] = p01; *(__nv_bfloat162*)&sAhi[o + 2] = p23;    \
        p01.x = l0; p01.y = l1; p23.x = l2; p23.y = l3;                            \
        *(__nv_bfloat162*)&sAlo[o] = p01; *(__nv_bfloat162*)&sAlo[o + 2] = p23;    \
    }

// per-warp max over the 8 edge rows of each point, via g-axis butterflies
#define EDGE_POOL_EPILOGUE()                                                       \
    _Pragma("unroll")                                                              \
    for (int mb = 0; mb < 2; ++mb)                                                 \
    _Pragma("unroll")                                                              \
    for (int nt = 0; nt < 8; ++nt)                                                 \
    _Pragma("unroll")                                                              \
    for (int e = 0; e < 4; ++e) {                                                  \
        float v = acc[mb][nt][e];                                                  \
        v = fmaxf(v, __shfl_xor_sync(0xffffffffu, v, 4));                          \
        v = fmaxf(v, __shfl_xor_sync(0xffffffffu, v, 8));                          \
        v = fmaxf(v, __shfl_xor_sync(0xffffffffu, v, 16));                         \
        acc[mb][nt][e] = v;                                                        \
    }                                                                              \
    if (g == 0) {                                                                  \
        _Pragma("unroll")                                                          \
        for (int mb = 0; mb < 2; ++mb)                                             \
        _Pragma("unroll")                                                          \
        for (int nt = 0; nt < 8; ++nt)                                             \
        _Pragma("unroll")                                                          \
        for (int e = 0; e < 4; ++e) {                                              \
            int point = wm * 4 + mb * 2 + (e >> 1);                                \
            int col = wn * 64 + nt * 8 + tig * 2 + (e & 1);                        \
            sRed[point * 132 + col] = acc[mb][nt][e];                              \
        }                                                                          \
    }                                                                              \
    __syncthreads();

// ---------------------------------------------------------------------------
// edge1: x1 = relu( max_k relu(a1[i]+c1[j]) @ W2 + b2 );  K=64, N=128
// ---------------------------------------------------------------------------
__global__ void __launch_bounds__(256, 2)
edge1_kernel(const float* __restrict__ b2) {
    __shared__ __align__(16) char smraw[4 * 128 * SA * 2];
    __shared__ int sIdx[128];
    __nv_bfloat16* sAhi = (__nv_bfloat16*)smraw;
    __nv_bfloat16* sAlo = sAhi + 128 * SA;
    __nv_bfloat16* sBhi = sAlo + 128 * SA;
    __nv_bfloat16* sBlo = sBhi + 128 * SA;
    float* sRed = (float*)smraw;                   // reused after GEMM

    const int p0 = blockIdx.x * 16;
    if (threadIdx.x < 128) sIdx[threadIdx.x] = g_idx[p0 * KNB + threadIdx.x];
    __syncthreads();

    const __nv_bfloat16* Bhi_g = g_w2t_hi;
    const __nv_bfloat16* Blo_g = g_w2t_lo;

    GEMM_CORE(64, EDGE_A_BUILD(64, g_a1, g_c1))
    EDGE_POOL_EPILOGUE()

    for (int r = tid; r < 2048; r += 256) {
        int p = r >> 7, c = r & 127;
        g_x1[(p0 + p) * H1D + c] = fmaxf(sRed[p * 132 + c] + b2[c], 0.f);
    }
}

// ---------------------------------------------------------------------------
// pre2: a2 = x1 @ (W3a-W3b) + b3 ; c2 = x1 @ W3b.  M=128, N=128, K=128.
// ---------------------------------------------------------------------------
#define PRE2_A_BUILD()                                                             \
    const float* __restrict__ xrow = g_x1 + (r0 + fm) * H1D;                       \
    _Pragma("unroll")                                                              \
    for (int u = 0; u < 4; ++u) {                                                  \
        float4 a = *(const float4*)(xrow + kb + fq * 16 + u * 4);                  \
        __nv_bfloat16 h0, l0, h1, l1, h2, l2, h3, l3;                              \
        bsplit(a.x, h0, l0); bsplit(a.y, h1, l1);                                  \
        bsplit(a.z, h2, l2); bsplit(a.w, h3, l3);                                  \
        int o = fm * SA + fq * 16 + u * 4;                                         \
        __nv_bfloat162 p01; p01.x = h0; p01.y = h1;                                \
        __nv_bfloat162 p23; p23.x = h2; p23.y = h3;                                \
        *(__nv_bfloat162*)&sAhi[o] = p01; *(__nv_bfloat162*)&sAhi[o + 2] = p23;    \
        p01.x = l0; p01.y = l1; p23.x = l2; p23.y = l3;                            \
        *(__nv_bfloat162*)&sAlo[o] = p01; *(__nv_bfloat162*)&sAlo[o + 2] = p23;    \
    }

__global__ void __launch_bounds__(256, 2)
pre2_kernel(const float* __restrict__ b3) {
    __shared__ __align__(16) char smraw[4 * 128 * SA * 2];
    __nv_bfloat16* sAhi = (__nv_bfloat16*)smraw;
    __nv_bfloat16* sAlo = sAhi + 128 * SA;
    __nv_bfloat16* sBhi = sAlo + 128 * SA;
    __nv_bfloat16* sBlo = sBhi + 128 * SA;

    const int r0 = blockIdx.x * 128;
    const int half = blockIdx.y;
    const __nv_bfloat16* Bhi_g = g_w3t_hi + half * (H1D * H1D);
    const __nv_bfloat16* Blo_g = g_w3t_lo + half * (H1D * H1D);

    GEMM_CORE(128, PRE2_A_BUILD())

    float* __restrict__ outp = half ? g_c2 : g_a2;
#pragma unroll
    for (int mb = 0; mb < 2; ++mb) {
        int row = r0 + wm * 32 + mb * 16 + g;
#pragma unroll
        for (int nt = 0; nt < 8; ++nt) {
            int col = wn * 64 + nt * 8 + tig * 2;
            float bx = half ? 0.f : b3[col];
            float by = half ? 0.f : b3[col + 1];
            float2 v0 = make_float2(acc[mb][nt][0] + bx, acc[mb][nt][1] + by);
            float2 v1 = make_float2(acc[mb][nt][2] + bx, acc[mb][nt][3] + by);
            *(float2*)&outp[row * H1D + col] = v0;
            *(float2*)&outp[(row + 8) * H1D + col] = v1;
        }
    }
}

// ---------------------------------------------------------------------------
// edge2: out = max_k relu(a2[i]+c2[j]) @ W4 + b4.  K=128, N=256 (split by y).
// ---------------------------------------------------------------------------
__global__ void __launch_bounds__(256, 2)
edge2_kernel(const float* __restrict__ b4, float* __restrict__ out) {
    __shared__ __align__(16) char smraw[4 * 128 * SA * 2];
    __shared__ int sIdx[128];
    __nv_bfloat16* sAhi = (__nv_bfloat16*)smraw;
    __nv_bfloat16* sAlo = sAhi + 128 * SA;
    __nv_bfloat16* sBhi = sAlo + 128 * SA;
    __nv_bfloat16* sBlo = sBhi + 128 * SA;
    float* sRed = (float*)smraw;

    const int p0 = blockIdx.x * 16;
    const int nb = blockIdx.y * 128;
    if (threadIdx.x < 128) sIdx[threadIdx.x] = g_idx[p0 * KNB + threadIdx.x];
    __syncthreads();

    const __nv_bfloat16* Bhi_g = g_w4t_hi + nb * H1D;
    const __nv_bfloat16* Blo_g = g_w4t_lo + nb * H1D;

    GEMM_CORE(128, EDGE_A_BUILD(128, g_a2, g_c2))
    EDGE_POOL_EPILOGUE()

    for (int r = tid; r < 2048; r += 256) {
        int p = r >> 7, c = r & 127;
        out[(p0 + p) * OUTC + nb + c] = sRed[p * 132 + c] + b4[nb + c];
    }
}

// ---------------------------------------------------------------------------
extern "C" void kernel_launch(void* const* d_in, const int* in_sizes, int n_in,
                              void* d_out, int out_size) {
    const float* pts = (const float*)d_in[0];
    const float* W1  = (const float*)d_in[1];
    const float* b1  = (const float*)d_in[2];
    const float* W2  = (const float*)d_in[3];
    const float* b2  = (const float*)d_in[4];
    const float* W3  = (const float*)d_in[5];
    const float* b3  = (const float*)d_in[6];
    const float* W4  = (const float*)d_in[7];
    const float* b4  = (const float*)d_in[8];
    float* out = (float*)d_out;

    prep_w2<<<(H1D * H0D) / 256, 256>>>(W2);
    prep_w3<<<(2 * H1D * H1D) / 256, 256>>>(W3);
    prep_w4<<<(OUTC * H1D) / 256, 256>>>(W4);
    knn_kernel<<<NPTS / 32, 256>>>(pts);
    pre1_kernel<<<NPTS * H0D / 256, 256>>>(pts, W1, b1);
    edge1_kernel<<<NPTS / 16, 256>>>(b2);
    pre2_kernel<<<dim3(NPTS / 128, 2), 256>>>(b3);
    edge2_kernel<<<dim3(NPTS / 16, 2), 256>>>(b4, out);
}

// round 7
// speedup vs baseline: 2.6455x; 1.1388x over previous
#include <cuda_runtime.h>
#include <cuda_bf16.h>
#include <float.h>
#include <stdint.h>

#define NPTS 8192
#define KNB  8
#define H0D  64
#define H1D  128
#define OUTC 256
#define SA   40          // smem row stride (bf16) -> conflict-free fragment LDS

// ---------------- scratch (static device globals) ----------------
__device__ int   g_idx[NPTS * KNB];
__device__ float g_a1[NPTS * H0D];
__device__ float g_c1[NPTS * H0D];
__device__ float g_x1[NPTS * H1D];
__device__ float g_a2[NPTS * H1D];
__device__ float g_c2[NPTS * H1D];

// weights: bf16 hi/lo split, transposed to [N][K]
__device__ __nv_bfloat16 g_w2t_hi[H1D * H0D],     g_w2t_lo[H1D * H0D];      // [128][64]
__device__ __nv_bfloat16 g_w3t_hi[2 * H1D * H1D], g_w3t_lo[2 * H1D * H1D];  // [2][128][128]
__device__ __nv_bfloat16 g_w4t_hi[OUTC * H1D],    g_w4t_lo[OUTC * H1D];     // [256][128]

// ---------------- helpers ----------------
__device__ __forceinline__ void bsplit(float v, __nv_bfloat16& h, __nv_bfloat16& l) {
    h = __float2bfloat16_rn(v);
    l = __float2bfloat16_rn(v - __bfloat162float(h));
}

__device__ __forceinline__ void mma16816(float* c, const uint32_t* a, const uint32_t* b) {
    asm volatile(
        "mma.sync.aligned.m16n8k16.row.col.f32.bf16.bf16.f32 "
        "{%0,%1,%2,%3}, {%4,%5,%6,%7}, {%8,%9}, {%0,%1,%2,%3};\n"
        : "+f"(c[0]), "+f"(c[1]), "+f"(c[2]), "+f"(c[3])
        : "r"(a[0]), "r"(a[1]), "r"(a[2]), "r"(a[3]), "r"(b[0]), "r"(b[1]));
}

// ---------------------------------------------------------------------------
// weight prep: split fp32 weights to bf16 hi/lo, transpose to [N][K]
// ---------------------------------------------------------------------------
__global__ void prep_w2(const float* __restrict__ W2) {
    int t = blockIdx.x * 256 + threadIdx.x;      // 8192 = 128n * 64k
    int n = t >> 6, k = t & 63;
    bsplit(W2[k * H1D + n], g_w2t_hi[t], g_w2t_lo[t]);
}
__global__ void prep_w3(const float* __restrict__ W3) {
    int t = blockIdx.x * 256 + threadIdx.x;      // 32768 = 2 * 128n * 128k
    int half = t >> 14; int r = t & 16383; int n = r >> 7; int k = r & 127;
    float v = W3[(H1D + k) * H1D + n];
    if (half == 0) v = W3[k * H1D + n] - v;
    bsplit(v, g_w3t_hi[t], g_w3t_lo[t]);
}
__global__ void prep_w4(const float* __restrict__ W4) {
    int t = blockIdx.x * 256 + threadIdx.x;      // 32768 = 256n * 128k
    int n = t >> 7, k = t & 127;
    bsplit(W4[k * OUTC + n], g_w4t_hi[t], g_w4t_lo[t]);
}

// ---------------------------------------------------------------------------
// KNN v3: threshold-filtered two-pass.
// 32 queries/block, 8 threads/query; d' = |p|^2 - 2 q·p (q-constant dropped;
// same rounding in both passes so the tau comparison is exact).
// Pass 1 (branchless): each thread takes the min d' over its 1024-candidate
//   shard; tau = max over the query's 8 shard-mins (>= true 8th distance,
//   since the 8 shard-min elements are 8 distinct candidates).
// Pass 2: sorted top-8 insert, gated by d <= tau -> ~2.8 inserts/thread, so
//   the divergent insert chain is issued ~8% of iterations instead of ~66%.
// Merge: unchanged 64-way (d, idx)-lexicographic merge per query.
// ---------------------------------------------------------------------------
__global__ void knn_kernel(const float* __restrict__ pts) {
    __shared__ float4 sP[512];
    __shared__ float  sD[32][65];
    __shared__ int    sI[32][65];

    const int tid = threadIdx.x;
    const int ql = tid >> 3, sh = tid & 7;
    const int q = blockIdx.x * 32 + ql;

    const float qx = pts[q * 3 + 0], qy = pts[q * 3 + 1], qz = pts[q * 3 + 2];
    const float qx2 = -2.0f * qx, qy2 = -2.0f * qy, qz2 = -2.0f * qz;

    // ---- pass 1: branchless per-shard min ----
    float mymin = FLT_MAX;
    for (int t0 = 0; t0 < NPTS; t0 += 512) {
        __syncthreads();
        for (int j = tid; j < 512; j += 256) {
            float x = pts[(t0 + j) * 3 + 0];
            float y = pts[(t0 + j) * 3 + 1];
            float z = pts[(t0 + j) * 3 + 2];
            sP[j] = make_float4(x, y, z, fmaf(z, z, fmaf(y, y, x * x)));
        }
        __syncthreads();
#pragma unroll 8
        for (int jj = sh; jj < 512; jj += 8) {
            float4 p = sP[jj];
            float d = fmaf(qz2, p.z, fmaf(qy2, p.y, fmaf(qx2, p.x, p.w)));
            mymin = fminf(mymin, d);
        }
    }
    // tau = max over this query's 8 shard mins (lanes (ql&3)*8 + 0..7)
    float tau = mymin;
    tau = fmaxf(tau, __shfl_xor_sync(0xffffffffu, tau, 1));
    tau = fmaxf(tau, __shfl_xor_sync(0xffffffffu, tau, 2));
    tau = fmaxf(tau, __shfl_xor_sync(0xffffffffu, tau, 4));

    // ---- pass 2: filtered top-8 insert ----
    float kd[KNB]; int ki[KNB];
#pragma unroll
    for (int s = 0; s < KNB; ++s) { kd[s] = FLT_MAX; ki[s] = 0x7fffffff; }

    for (int t0 = 0; t0 < NPTS; t0 += 512) {
        __syncthreads();
        for (int j = tid; j < 512; j += 256) {
            float x = pts[(t0 + j) * 3 + 0];
            float y = pts[(t0 + j) * 3 + 1];
            float z = pts[(t0 + j) * 3 + 2];
            sP[j] = make_float4(x, y, z, fmaf(z, z, fmaf(y, y, x * x)));
        }
        __syncthreads();
#pragma unroll 4
        for (int jj = sh; jj < 512; jj += 8) {
            float4 p = sP[jj];
            float d = fmaf(qz2, p.z, fmaf(qy2, p.y, fmaf(qx2, p.x, p.w)));
            if (d <= tau) {
                if (d < kd[KNB - 1]) {       // strict: equal-d keeps earlier index
                    kd[KNB - 1] = d; ki[KNB - 1] = t0 + jj;
#pragma unroll
                    for (int s = KNB - 1; s > 0; --s) {
                        if (kd[s] < kd[s - 1]) {
                            float td = kd[s]; kd[s] = kd[s - 1]; kd[s - 1] = td;
                            int   ti = ki[s]; ki[s] = ki[s - 1]; ki[s - 1] = ti;
                        } else break;
                    }
                }
            }
        }
    }
#pragma unroll
    for (int s = 0; s < KNB; ++s) { sD[ql][sh * 8 + s] = kd[s]; sI[ql][sh * 8 + s] = ki[s]; }
    __syncthreads();

    if (tid < 32) {
        float md[KNB]; int mi[KNB];
#pragma unroll
        for (int s = 0; s < KNB; ++s) { md[s] = FLT_MAX; mi[s] = 0x7fffffff; }
        for (int e = 0; e < 64; ++e) {
            float d = sD[tid][e]; int i = sI[tid][e];
            if (d < md[KNB - 1] || (d == md[KNB - 1] && i < mi[KNB - 1])) {
                md[KNB - 1] = d; mi[KNB - 1] = i;
#pragma unroll
                for (int s = KNB - 1; s > 0; --s) {
                    if (md[s] < md[s - 1] || (md[s] == md[s - 1] && mi[s] < mi[s - 1])) {
                        float td = md[s]; md[s] = md[s - 1]; md[s - 1] = td;
                        int   ti = mi[s]; mi[s] = mi[s - 1]; mi[s - 1] = ti;
                    } else break;
                }
            }
        }
        int qq = blockIdx.x * 32 + tid;
#pragma unroll
        for (int s = 0; s < KNB; ++s) g_idx[qq * KNB + s] = mi[s];
    }
}

// ---------------------------------------------------------------------------
// pre1 (unchanged)
// ---------------------------------------------------------------------------
__global__ void pre1_kernel(const float* __restrict__ pts,
                            const float* __restrict__ W1,
                            const float* __restrict__ b1) {
    int t = blockIdx.x * blockDim.x + threadIdx.x;
    int i = t >> 6, h = t & 63;
    float x = pts[i * 3 + 0], y = pts[i * 3 + 1], z = pts[i * 3 + 2];
    float wa0 = W1[0 * 64 + h], wa1 = W1[1 * 64 + h], wa2 = W1[2 * 64 + h];
    float wb0 = W1[3 * 64 + h], wb1 = W1[4 * 64 + h], wb2 = W1[5 * 64 + h];
    float c = fmaf(z, wb2, fmaf(y, wb1, x * wb0));
    float a = fmaf(z, wa2 - wb2, fmaf(y, wa1 - wb1, x * (wa0 - wb0))) + b1[h];
    g_a1[t] = a;
    g_c1[t] = c;
}

// ===========================================================================
// Tensor-core edge GEMM (unchanged from round 6).
// ===========================================================================

#define GEMM_CORE(KDIM, A_BUILD)                                                   \
    const int tid = threadIdx.x;                                                   \
    const int lane = tid & 31, wid = tid >> 5;                                     \
    const int g = lane >> 2, tig = lane & 3;                                       \
    const int wm = wid & 3, wn = wid >> 2;                                         \
    const int fm = tid & 127, fq = tid >> 7;                                       \
    float acc[2][8][4];                                                            \
    _Pragma("unroll") for (int mb = 0; mb < 2; ++mb)                               \
    _Pragma("unroll") for (int nt = 0; nt < 8; ++nt)                               \
    _Pragma("unroll") for (int e = 0; e < 4; ++e) acc[mb][nt][e] = 0.f;            \
    for (int kb = 0; kb < (KDIM); kb += 32) {                                      \
        { A_BUILD }                                                                \
        {   /* stage B: [n][k] rows, 16 bf16 per thread per buffer */              \
            const __nv_bfloat16* bh = Bhi_g + fm * (KDIM) + kb + fq * 16;          \
            const __nv_bfloat16* bl = Blo_g + fm * (KDIM) + kb + fq * 16;          \
            int o = fm * SA + fq * 16;                                             \
            *(uint4*)&sBhi[o]     = *(const uint4*)(bh);                           \
            *(uint4*)&sBhi[o + 8] = *(const uint4*)(bh + 8);                       \
            *(uint4*)&sBlo[o]     = *(const uint4*)(bl);                           \
            *(uint4*)&sBlo[o + 8] = *(const uint4*)(bl + 8);                       \
        }                                                                          \
        __syncthreads();                                                           \
        _Pragma("unroll")                                                          \
        for (int ks = 0; ks < 2; ++ks) {                                           \
            const int kc = ks * 16;                                                \
            _Pragma("unroll")                                                      \
            for (int t = 0; t < 3; ++t) {                                          \
                const __nv_bfloat16* Ap = (t == 2) ? sAlo : sAhi;                  \
                const __nv_bfloat16* Bp = (t == 1) ? sBlo : sBhi;                  \
                uint32_t af[2][4];                                                 \
                _Pragma("unroll")                                                  \
                for (int mb = 0; mb < 2; ++mb) {                                   \
                    int r = (wm * 32 + mb * 16 + g) * SA + kc + tig * 2;           \
                    af[mb][0] = *(const uint32_t*)(Ap + r);                        \
                    af[mb][1] = *(const uint32_t*)(Ap + r + 8 * SA);               \
                    af[mb][2] = *(const uint32_t*)(Ap + r + 8);                    \
                    af[mb][3] = *(const uint32_t*)(Ap + r + 8 * SA + 8);           \
                }                                                                  \
                uint32_t bf[8][2];                                                 \
                _Pragma("unroll")                                                  \
                for (int nt = 0; nt < 8; ++nt) {                                   \
                    int rB = (wn * 64 + nt * 8 + g) * SA + kc + tig * 2;           \
                    bf[nt][0] = *(const uint32_t*)(Bp + rB);                       \
                    bf[nt][1] = *(const uint32_t*)(Bp + rB + 8);                   \
                }                                                                  \
                _Pragma("unroll")                                                  \
                for (int mb = 0; mb < 2; ++mb)                                     \
                _Pragma("unroll")                                                  \
                for (int nt = 0; nt < 8; ++nt)                                     \
                    mma16816(acc[mb][nt], af[mb], bf[nt]);                         \
            }                                                                      \
        }                                                                          \
        __syncthreads();                                                           \
    }

#define EDGE_A_BUILD(KDIM, ASRC, CSRC)                                             \
    const float* __restrict__ arow = (ASRC) + (p0 + (fm >> 3)) * (KDIM);           \
    const float* __restrict__ crow = (CSRC) + sIdx[fm] * (KDIM);                   \
    _Pragma("unroll")                                                              \
    for (int u = 0; u < 4; ++u) {                                                  \
        float4 a = *(const float4*)(arow + kb + fq * 16 + u * 4);                  \
        float4 c = *(const float4*)(crow + kb + fq * 16 + u * 4);                  \
        float v0 = fmaxf(a.x + c.x, 0.f), v1 = fmaxf(a.y + c.y, 0.f);              \
        float v2 = fmaxf(a.z + c.z, 0.f), v3 = fmaxf(a.w + c.w, 0.f);              \
        __nv_bfloat16 h0, l0, h1, l1, h2, l2, h3, l3;                              \
        bsplit(v0, h0, l0); bsplit(v1, h1, l1);                                    \
        bsplit(v2, h2, l2); bsplit(v3, h3, l3);                                    \
        int o = fm * SA + fq * 16 + u * 4;                                         \
        __nv_bfloat162 p01; p01.x = h0; p01.y = h1;                                \
        __nv_bfloat162 p23; p23.x = h2; p23.y = h3;                                \
        *(__nv_bfloat162*)&sAhi[o] = p01; *(__nv_bfloat162*)&sAhi[o + 2] = p23;    \
        p01.x = l0; p01.y = l1; p23.x = l2; p23.y = l3;                            \
        *(__nv_bfloat162*)&sAlo[o] = p01; *(__nv_bfloat162*)&sAlo[o + 2] = p23;    \
    }

#define EDGE_POOL_EPILOGUE()                                                       \
    _Pragma("unroll")                                                              \
    for (int mb = 0; mb < 2; ++mb)                                                 \
    _Pragma("unroll")                                                              \
    for (int nt = 0; nt < 8; ++nt)                                                 \
    _Pragma("unroll")                                                              \
    for (int e = 0; e < 4; ++e) {                                                  \
        float v = acc[mb][nt][e];                                                  \
        v = fmaxf(v, __shfl_xor_sync(0xffffffffu, v, 4));                          \
        v = fmaxf(v, __shfl_xor_sync(0xffffffffu, v, 8));                          \
        v = fmaxf(v, __shfl_xor_sync(0xffffffffu, v, 16));                         \
        acc[mb][nt][e] = v;                                                        \
    }                                                                              \
    if (g == 0) {                                                                  \
        _Pragma("unroll")                                                          \
        for (int mb = 0; mb < 2; ++mb)                                             \
        _Pragma("unroll")                                                          \
        for (int nt = 0; nt < 8; ++nt)                                             \
        _Pragma("unroll")                                                          \
        for (int e = 0; e < 4; ++e) {                                              \
            int point = wm * 4 + mb * 2 + (e >> 1);                                \
            int col = wn * 64 + nt * 8 + tig * 2 + (e & 1);                        \
            sRed[point * 132 + col] = acc[mb][nt][e];                              \
        }                                                                          \
    }                                                                              \
    __syncthreads();

// ---------------------------------------------------------------------------
// edge1: x1 = relu( max_k relu(a1[i]+c1[j]) @ W2 + b2 );  K=64, N=128
// ---------------------------------------------------------------------------
__global__ void __launch_bounds__(256, 2)
edge1_kernel(const float* __restrict__ b2) {
    __shared__ __align__(16) char smraw[4 * 128 * SA * 2];
    __shared__ int sIdx[128];
    __nv_bfloat16* sAhi = (__nv_bfloat16*)smraw;
    __nv_bfloat16* sAlo = sAhi + 128 * SA;
    __nv_bfloat16* sBhi = sAlo + 128 * SA;
    __nv_bfloat16* sBlo = sBhi + 128 * SA;
    float* sRed = (float*)smraw;                   // reused after GEMM

    const int p0 = blockIdx.x * 16;
    if (threadIdx.x < 128) sIdx[threadIdx.x] = g_idx[p0 * KNB + threadIdx.x];
    __syncthreads();

    const __nv_bfloat16* Bhi_g = g_w2t_hi;
    const __nv_bfloat16* Blo_g = g_w2t_lo;

    GEMM_CORE(64, EDGE_A_BUILD(64, g_a1, g_c1))
    EDGE_POOL_EPILOGUE()

    for (int r = tid; r < 2048; r += 256) {
        int p = r >> 7, c = r & 127;
        g_x1[(p0 + p) * H1D + c] = fmaxf(sRed[p * 132 + c] + b2[c], 0.f);
    }
}

// ---------------------------------------------------------------------------
// pre2: a2 = x1 @ (W3a-W3b) + b3 ; c2 = x1 @ W3b.  M=128, N=128, K=128.
// ---------------------------------------------------------------------------
#define PRE2_A_BUILD()                                                             \
    const float* __restrict__ xrow = g_x1 + (r0 + fm) * H1D;                       \
    _Pragma("unroll")                                                              \
    for (int u = 0; u < 4; ++u) {                                                  \
        float4 a = *(const float4*)(xrow + kb + fq * 16 + u * 4);                  \
        __nv_bfloat16 h0, l0, h1, l1, h2, l2, h3, l3;                              \
        bsplit(a.x, h0, l0); bsplit(a.y, h1, l1);                                  \
        bsplit(a.z, h2, l2); bsplit(a.w, h3, l3);                                  \
        int o = fm * SA + fq * 16 + u * 4;                                         \
        __nv_bfloat162 p01; p01.x = h0; p01.y = h1;                                \
        __nv_bfloat162 p23; p23.x = h2; p23.y = h3;                                \
        *(__nv_bfloat162*)&sAhi[o] = p01; *(__nv_bfloat162*)&sAhi[o + 2] = p23;    \
        p01.x = l0; p01.y = l1; p23.x = l2; p23.y = l3;                            \
        *(__nv_bfloat162*)&sAlo[o] = p01; *(__nv_bfloat162*)&sAlo[o + 2] = p23;    \
    }

__global__ void __launch_bounds__(256, 2)
pre2_kernel(const float* __restrict__ b3) {
    __shared__ __align__(16) char smraw[4 * 128 * SA * 2];
    __nv_bfloat16* sAhi = (__nv_bfloat16*)smraw;
    __nv_bfloat16* sAlo = sAhi + 128 * SA;
    __nv_bfloat16* sBhi = sAlo + 128 * SA;
    __nv_bfloat16* sBlo = sBhi + 128 * SA;

    const int r0 = blockIdx.x * 128;
    const int half = blockIdx.y;
    const __nv_bfloat16* Bhi_g = g_w3t_hi + half * (H1D * H1D);
    const __nv_bfloat16* Blo_g = g_w3t_lo + half * (H1D * H1D);

    GEMM_CORE(128, PRE2_A_BUILD())

    float* __restrict__ outp = half ? g_c2 : g_a2;
#pragma unroll
    for (int mb = 0; mb < 2; ++mb) {
        int row = r0 + wm * 32 + mb * 16 + g;
#pragma unroll
        for (int nt = 0; nt < 8; ++nt) {
            int col = wn * 64 + nt * 8 + tig * 2;
            float bx = half ? 0.f : b3[col];
            float by = half ? 0.f : b3[col + 1];
            float2 v0 = make_float2(acc[mb][nt][0] + bx, acc[mb][nt][1] + by);
            float2 v1 = make_float2(acc[mb][nt][2] + bx, acc[mb][nt][3] + by);
            *(float2*)&outp[row * H1D + col] = v0;
            *(float2*)&outp[(row + 8) * H1D + col] = v1;
        }
    }
}

// ---------------------------------------------------------------------------
// edge2: out = max_k relu(a2[i]+c2[j]) @ W4 + b4.  K=128, N=256 (split by y).
// ---------------------------------------------------------------------------
__global__ void __launch_bounds__(256, 2)
edge2_kernel(const float* __restrict__ b4, float* __restrict__ out) {
    __shared__ __align__(16) char smraw[4 * 128 * SA * 2];
    __shared__ int sIdx[128];
    __nv_bfloat16* sAhi = (__nv_bfloat16*)smraw;
    __nv_bfloat16* sAlo = sAhi + 128 * SA;
    __nv_bfloat16* sBhi = sAlo + 128 * SA;
    __nv_bfloat16* sBlo = sBhi + 128 * SA;
    float* sRed = (float*)smraw;

    const int p0 = blockIdx.x * 16;
    const int nb = blockIdx.y * 128;
    if (threadIdx.x < 128) sIdx[threadIdx.x] = g_idx[p0 * KNB + threadIdx.x];
    __syncthreads();

    const __nv_bfloat16* Bhi_g = g_w4t_hi + nb * H1D;
    const __nv_bfloat16* Blo_g = g_w4t_lo + nb * H1D;

    GEMM_CORE(128, EDGE_A_BUILD(128, g_a2, g_c2))
    EDGE_POOL_EPILOGUE()

    for (int r = tid; r < 2048; r += 256) {
        int p = r >> 7, c = r & 127;
        out[(p0 + p) * OUTC + nb + c] = sRed[p * 132 + c] + b4[nb + c];
    }
}

// ---------------------------------------------------------------------------
extern "C" void kernel_launch(void* const* d_in, const int* in_sizes, int n_in,
                              void* d_out, int out_size) {
    const float* pts = (const float*)d_in[0];
    const float* W1  = (const float*)d_in[1];
    const float* b1  = (const float*)d_in[2];
    const float* W2  = (const float*)d_in[3];
    const float* b2  = (const float*)d_in[4];
    const float* W3  = (const float*)d_in[5];
    const float* b3  = (const float*)d_in[6];
    const float* W4  = (const float*)d_in[7];
    const float* b4  = (const float*)d_in[8];
    float* out = (float*)d_out;

    prep_w2<<<(H1D * H0D) / 256, 256>>>(W2);
    prep_w3<<<(2 * H1D * H1D) / 256, 256>>>(W3);
    prep_w4<<<(OUTC * H1D) / 256, 256>>>(W4);
    knn_kernel<<<NPTS / 32, 256>>>(pts);
    pre1_kernel<<<NPTS * H0D / 256, 256>>>(pts, W1, b1);
    edge1_kernel<<<NPTS / 16, 256>>>(b2);
    pre2_kernel<<<dim3(NPTS / 128, 2), 256>>>(b3);
    edge2_kernel<<<dim3(NPTS / 16, 2), 256>>>(b4, out);
}